// round 6
// baseline (speedup 1.0000x reference)
#include <cuda_runtime.h>
#include <cstdint>
#include <cstddef>

#define EPSV 1e-5f

// ---------------------------------------------------------------------------
// Problem constants
//   branches (order): cA3(L=24), cD3(L=24), cD2(L=47), cD1(L=94)
//   conv K=3, OUT_CH=16, POOL=2
//   Lp = {11,11,22,46}; bits/branch = 16*Lp = {176,176,352,736}; total 1440
//   bit offsets OFF = {0,176,352,704}
//
//   Feature bit layout (ours): d = OFF + 16*i + (15 - c)  [position-major,
//   channel REVERSED inside the 16-bit group: funnel-shift accumulation
//   pushes c=0 to the MSB of the group], and the stored bit is the
//   COMPLEMENT (1 = pooled value negative). The same permutation is applied
//   to fc1_w's packed bits; the complement is folded into the FC1 threshold:
//   dot = 2*P' - 1440, P' = popc(F' ^ W).
// ---------------------------------------------------------------------------

struct Ptrs {
    const float* x[4];
    const float* w[4];
    const float* g[4];
    const float* b[4];
    const float* m[4];
    const float* v[4];
    const float* fc1_w;
    const float* g1; const float* b1; const float* m1; const float* v1;
    const float* fc2_w; const float* fc2_b;
};

// Precomputed parameter scratch (static device arrays: allocation-free)
__device__ uint32_t           g_wbits[64 * 48]; // permuted fc1_w sign bits, row stride 48
__device__ int                g_thr[64];        // integer popc thresholds: h' = (P' > T) ? +1 : -1
__device__ unsigned long long g_bconsP[64 * 4]; // [br*16+c]*4 = dup-packed {q0,q0},{q1,q1},{q2,q2},{C,C}
__device__ float              g_fc2t[64 * 8];   // transposed fc2_w * s_j : [j*8+o]

// ---- packed f32x2 helpers (sm_103a) ---------------------------------------
__device__ __forceinline__ unsigned long long pack2(float lo, float hi) {
    unsigned long long r;
    asm("mov.b64 %0, {%1, %2};" : "=l"(r) : "r"(__float_as_uint(lo)), "r"(__float_as_uint(hi)));
    return r;
}
__device__ __forceinline__ unsigned long long fma2(unsigned long long a,
                                                   unsigned long long b,
                                                   unsigned long long c) {
    unsigned long long d;
    asm("fma.rn.f32x2 %0, %1, %2, %3;" : "=l"(d) : "l"(a), "l"(b), "l"(c));
    return d;
}

// ---------------------------------------------------------------------------
// Prep kernel: pack fc1 weight bits (permuted) + fold BN params.
// grid = 360 blocks * 256 thr = 2880 warps = 64 rows * 45 words (exact).
// ---------------------------------------------------------------------------
__global__ void prep_kernel(Ptrs p)
{
    const int t    = blockIdx.x * 256 + threadIdx.x;
    const int gw   = t >> 5;
    const int lane = t & 31;

    // ---- pack one 32-bit word of permuted fc1 weight sign bits per warp ----
    {
        const int j = gw / 45;       // fc1 output row
        const int w = gw - j * 45;   // feature word
        const int d = w * 32 + lane; // permuted bit index
        // d = OFF + 16*i + (15 - c)  ->  src = OFF + c*Lp + i
        int src;
        if (d < 176)      { int r = d;       src =       (15 - (r & 15)) * 11 + (r >> 4); }
        else if (d < 352) { int r = d - 176; src = 176 + (15 - (r & 15)) * 11 + (r >> 4); }
        else if (d < 704) { int r = d - 352; src = 352 + (15 - (r & 15)) * 22 + (r >> 4); }
        else              { int r = d - 704; src = 704 + (15 - (r & 15)) * 46 + (r >> 4); }
        const unsigned bal =
            __ballot_sync(0xffffffffu, p.fc1_w[j * 1440 + src] > 0.0f);
        if (lane == 0) g_wbits[j * 48 + w] = bal;
    }

    // ---- fold BN params (block 0 only) ----
    if (blockIdx.x == 0) {
        const int tid = threadIdx.x;
        if (tid < 64) {
            // FC1 BN with complemented features:
            //   val = inv*(2P' - 1440 - m1) + b1 = slope*P' + A,
            //   slope = 2*inv, A = b1 - inv*(1440 + m1)
            // Reduce sign(val) to an integer compare on P':
            //   slope > 0: val>0 <=> P' > floor(-A/slope)            (s=+1)
            //   slope < 0: val>0 <=> P' < ceil(-A/slope) <=> !(P' > ceil-1), fold s=-1
            const float inv   = p.g1[tid] * rsqrtf(p.v1[tid] + EPSV);
            const float slope = 2.0f * inv;
            const float A     = p.b1[tid] - inv * (1440.0f + p.m1[tid]);
            float tthr = -A / slope;
            tthr = fmaxf(fminf(tthr, 2.0e9f), -2.0e9f);   // clamp before int cast
            int   T;
            float s;
            if (slope > 0.0f) { T = (int)floorf(tthr);        s =  1.0f; }
            else              { T = (int)ceilf(tthr) - 1;     s = -1.0f; }
            g_thr[tid] = T;
            // FC2 transpose with s_j folded in (row stride 8 for LDS.128)
            #pragma unroll
            for (int o = 0; o < 5; o++) g_fc2t[tid * 8 + o] = s * p.fc2_w[o * 64 + tid];
            #pragma unroll
            for (int o = 5; o < 8; o++) g_fc2t[tid * 8 + o] = 0.0f;
        }
        if (tid >= 64 && tid < 128) {
            const int id = tid - 64;
            const int br = id >> 4, c = id & 15;
            const float* wc = p.w[br] + c * 3;   // (OUT_CH,1,K) row-major
            const float inv = p.g[br][c] * rsqrtf(p.v[br][c] + EPSV);
            float q[3];
            #pragma unroll
            for (int k = 0; k < 3; k++) {
                const float wk = wc[k];
                const float sg = (wk > 0.0f) ? 1.0f : ((wk < 0.0f) ? -1.0f : 0.0f);
                q[k] = inv * sg;
            }
            const float C = p.b[br][c] - inv * p.m[br][c];
            // duplicated packed pairs -> main kernel does zero re-pack MOVs
            g_bconsP[id * 4 + 0] = pack2(q[0], q[0]);
            g_bconsP[id * 4 + 1] = pack2(q[1], q[1]);
            g_bconsP[id * 4 + 2] = pack2(q[2], q[2]);
            g_bconsP[id * 4 + 3] = pack2(C,    C);
        }
    }
}

// ---------------------------------------------------------------------------
// Main kernel: 64 samples per CTA, 1024 CTAs, up to 7 CTAs/SM (single wave).
// ---------------------------------------------------------------------------
static constexpr int TPB     = 64;
static constexpr int XSTRIDE = 53;   // odd -> conflict-free per-row LDS

// Coalesced staging of x[s0+s][XB .. XB+XL) into smem tile (row stride 53).
// FULLY UNROLLED so ptxas front-batches the LDGs (MLP ~ XL) instead of
// serializing each LDG->STS pair at one memory latency.
template <int L, int XB, int XL>
__device__ __forceinline__ void load_chunk(float* s_x, const float* __restrict__ xg,
                                           int s0, int tid)
{
    #pragma unroll
    for (int k = 0; k < XL; k++) {
        const int idx  = tid + k * TPB;          // < TPB*XL
        const int s    = idx / XL;               // compile-time-const divisor
        const int pcol = idx - s * XL;
        s_x[s * XSTRIDE + pcol] = __ldg(&xg[(size_t)(s0 + s) * L + XB + pcol]);
    }
}

// Compute NP pooled positions starting at P0 of one branch using packed
// f32x2 FMAs: lanes (lo,hi) = (zA,zB) of one pooled pair.
// COMPLEMENT bit (1 = pooled max <= 0, i.e. both lanes negative):
//   u = lo & hi  (bit31 = signA AND signB, one LOP3)
//   mc = (mc << 1) | (u >> 31)  (one SHF via funnel shift)
// -> 2 alu ops per (channel, position); channel c lands at group bit 15-c.
template <int OFF, int XB, int P0, int NP>
__device__ __forceinline__ void proc_chunk(uint32_t f[45], const float* xrow,
                                           const unsigned long long* bcp)
{
    // overlapping packed pairs (x[2P0+i], x[2P0+i+1]) — invariant over channels
    unsigned long long xp[2 * NP + 1];
    #pragma unroll
    for (int i = 0; i < 2 * NP + 1; i++) {
        const int b = 2 * P0 - XB + i;
        xp[i] = pack2(xrow[b], xrow[b + 1]);
    }

    uint32_t mc[NP];
    #pragma unroll
    for (int i = 0; i < NP; i++) mc[i] = 0u;

    #pragma unroll 1
    for (int c = 0; c < 16; c++) {
        // two LDS.128 (broadcast): {q0,q0},{q1,q1} and {q2,q2},{C,C}
        const ulonglong2 qa = *reinterpret_cast<const ulonglong2*>(bcp + 4 * c);
        const ulonglong2 qb = *reinterpret_cast<const ulonglong2*>(bcp + 4 * c + 2);
        #pragma unroll
        for (int ip = 0; ip < NP; ip++) {
            unsigned long long acc = fma2(qb.x, xp[2 * ip + 2], qb.y);
            acc = fma2(qa.y, xp[2 * ip + 1], acc);
            acc = fma2(qa.x, xp[2 * ip + 0], acc);
            const uint32_t u = (uint32_t)acc & (uint32_t)(acc >> 32);  // LOP3
            mc[ip] = __funnelshift_l(u, mc[ip], 1);                    // SHF
        }
    }
    #pragma unroll
    for (int ip = 0; ip < NP; ip++) {
        const int d = OFF + 16 * (P0 + ip);          // compile-time
        f[d >> 5] |= mc[ip] << (d & 31);             // shift is 0 or 16
    }
}

__global__ void __launch_bounds__(TPB, 7)
wavebnn_kernel(Ptrs p, float* __restrict__ out)
{
    __shared__ __align__(16) uint32_t s_wbits[64 * 48];
    __shared__ int s_thr[64];
    __shared__ __align__(16) unsigned long long s_bconsP[64 * 4];
    __shared__ __align__(16) float s_fc2t[64 * 8];
    __shared__ float s_x[TPB * XSTRIDE];

    const int tid = threadIdx.x;
    const int s0  = blockIdx.x * TPB;

    // ---- stage constants: FULLY UNROLLED so all LDGs front-batch (one
    // latency exposure, not one per iteration).
    #pragma unroll
    for (int k = 0; k < 48; k++) s_wbits[tid + k * TPB] = g_wbits[tid + k * TPB];
    #pragma unroll
    for (int k = 0; k < 8; k++)  s_fc2t[tid + k * TPB] = g_fc2t[tid + k * TPB];
    #pragma unroll
    for (int k = 0; k < 4; k++)  s_bconsP[tid + k * TPB] = g_bconsP[tid + k * TPB];
    s_thr[tid] = g_thr[tid];
    // phase-1 x load overlaps the constant staging (same pre-barrier region)
    load_chunk<24, 0, 24>(s_x, p.x[0], s0, tid);

    uint32_t f[45];
    #pragma unroll
    for (int i = 0; i < 45; i++) f[i] = 0u;

    const float* xrow = &s_x[tid * XSTRIDE];

    // ---- phase 1: cA3 (L=24, Lp=11, OFF=0) ----
    __syncthreads();
    proc_chunk<0, 0, 0, 8>(f, xrow, s_bconsP + 0 * 64);
    proc_chunk<0, 0, 8, 3>(f, xrow, s_bconsP + 0 * 64);

    // ---- phase 2: cD3 (L=24, Lp=11, OFF=176) ----
    __syncthreads();
    load_chunk<24, 0, 24>(s_x, p.x[1], s0, tid);
    __syncthreads();
    proc_chunk<176, 0, 0, 8>(f, xrow, s_bconsP + 1 * 64);
    proc_chunk<176, 0, 8, 3>(f, xrow, s_bconsP + 1 * 64);

    // ---- phase 3: cD2 (L=47, Lp=22, OFF=352) ----
    __syncthreads();
    load_chunk<47, 0, 47>(s_x, p.x[2], s0, tid);
    __syncthreads();
    proc_chunk<352, 0,  0, 8>(f, xrow, s_bconsP + 2 * 64);
    proc_chunk<352, 0,  8, 8>(f, xrow, s_bconsP + 2 * 64);
    proc_chunk<352, 0, 16, 6>(f, xrow, s_bconsP + 2 * 64);

    // ---- phase 4: cD1 part 1 (L=94, OFF=704): cols [0,50), p=0..23 ----
    __syncthreads();
    load_chunk<94, 0, 50>(s_x, p.x[3], s0, tid);
    __syncthreads();
    proc_chunk<704, 0,  0, 8>(f, xrow, s_bconsP + 3 * 64);
    proc_chunk<704, 0,  8, 8>(f, xrow, s_bconsP + 3 * 64);
    proc_chunk<704, 0, 16, 8>(f, xrow, s_bconsP + 3 * 64);

    // ---- phase 5: cD1 part 2: cols [48,94), p=24..45 ----
    __syncthreads();
    load_chunk<94, 48, 46>(s_x, p.x[3], s0, tid);
    __syncthreads();
    proc_chunk<704, 48, 24, 8>(f, xrow, s_bconsP + 3 * 64);
    proc_chunk<704, 48, 32, 8>(f, xrow, s_bconsP + 3 * 64);
    proc_chunk<704, 48, 40, 6>(f, xrow, s_bconsP + 3 * 64);

    // ---- FC1 (XOR/POPC, pairwise IADD3 accumulation) + threshold + FC2 ----
    float o0 = p.fc2_b[0], o1 = p.fc2_b[1], o2 = p.fc2_b[2],
          o3 = p.fc2_b[3], o4 = p.fc2_b[4];

    #pragma unroll 1
    for (int j = 0; j < 64; j++) {
        const uint32_t* wr = &s_wbits[j * 48];
        int a0 = 0, a1 = 0;
        #pragma unroll
        for (int w4 = 0; w4 < 11; w4++) {
            const uint4 ww = *reinterpret_cast<const uint4*>(wr + 4 * w4);
            a0 += __popc(f[4*w4+0] ^ ww.x) + __popc(f[4*w4+1] ^ ww.y);   // IADD3
            a1 += __popc(f[4*w4+2] ^ ww.z) + __popc(f[4*w4+3] ^ ww.w);   // IADD3
        }
        const int P = a0 + a1 + __popc(f[44] ^ wr[44]);                  // IADD3

        const float h = (P > s_thr[j]) ? 1.0f : -1.0f;   // ISETP + SEL

        const float* w2 = &s_fc2t[j * 8];                // s_j pre-folded
        o0 = fmaf(h, w2[0], o0);
        o1 = fmaf(h, w2[1], o1);
        o2 = fmaf(h, w2[2], o2);
        o3 = fmaf(h, w2[3], o3);
        o4 = fmaf(h, w2[4], o4);
    }

    const size_t ob = (size_t)(s0 + tid) * 5;
    out[ob + 0] = o0; out[ob + 1] = o1; out[ob + 2] = o2;
    out[ob + 3] = o3; out[ob + 4] = o4;
}

// ---------------------------------------------------------------------------
// Launch
// ---------------------------------------------------------------------------
extern "C" void kernel_launch(void* const* d_in, const int* in_sizes, int n_in,
                              void* d_out, int out_size)
{
    (void)n_in; (void)out_size;
    Ptrs p;
    // Disambiguate metadata ordering:
    //  dict order      : per branch [x,w,g,b,m,v]        -> in_sizes[1] == 48
    //  signature order : x*4 then per branch [w,g,b,m,v] -> in_sizes[1] == 65536*24
    const bool dict = (in_sizes[1] == 48);
    for (int br = 0; br < 4; br++) {
        if (dict) {
            p.x[br] = (const float*)d_in[br * 6 + 0];
            p.w[br] = (const float*)d_in[br * 6 + 1];
            p.g[br] = (const float*)d_in[br * 6 + 2];
            p.b[br] = (const float*)d_in[br * 6 + 3];
            p.m[br] = (const float*)d_in[br * 6 + 4];
            p.v[br] = (const float*)d_in[br * 6 + 5];
        } else {
            p.x[br] = (const float*)d_in[br];
            p.w[br] = (const float*)d_in[4 + br * 5 + 0];
            p.g[br] = (const float*)d_in[4 + br * 5 + 1];
            p.b[br] = (const float*)d_in[4 + br * 5 + 2];
            p.m[br] = (const float*)d_in[4 + br * 5 + 3];
            p.v[br] = (const float*)d_in[4 + br * 5 + 4];
        }
    }
    p.fc1_w = (const float*)d_in[24];
    p.g1    = (const float*)d_in[25];
    p.b1    = (const float*)d_in[26];
    p.m1    = (const float*)d_in[27];
    p.v1    = (const float*)d_in[28];
    p.fc2_w = (const float*)d_in[29];
    p.fc2_b = (const float*)d_in[30];

    prep_kernel<<<360, 256>>>(p);
    wavebnn_kernel<<<65536 / TPB, TPB>>>(p, (float*)d_out);
}

// round 8
// speedup vs baseline: 1.0228x; 1.0228x over previous
#include <cuda_runtime.h>
#include <cstdint>
#include <cstddef>

#define EPSV 1e-5f

// ---------------------------------------------------------------------------
// Problem constants
//   branches (order): cA3(L=24), cD3(L=24), cD2(L=47), cD1(L=94)
//   conv K=3, OUT_CH=16, POOL=2
//   Lp = {11,11,22,46}; bits/branch = 16*Lp = {176,176,352,736}; total 1440
//   bit offsets OFF = {0,176,352,704}
//
//   Feature bit layout (ours): d = OFF + 16*i + (15 - c)  [position-major,
//   channel REVERSED inside the 16-bit group: funnel-shift accumulation
//   pushes c=0 to the MSB of the group], and the stored bit is the
//   COMPLEMENT (1 = pooled value negative). The same permutation is applied
//   to fc1_w's packed bits; the complement is folded into the FC1 threshold:
//   dot = 2*P' - 1440, P' = popc(F' ^ W).
// ---------------------------------------------------------------------------

struct Ptrs {
    const float* x[4];
    const float* w[4];
    const float* g[4];
    const float* b[4];
    const float* m[4];
    const float* v[4];
    const float* fc1_w;
    const float* g1; const float* b1; const float* m1; const float* v1;
    const float* fc2_w; const float* fc2_b;
};

// Precomputed parameter scratch (static device arrays: allocation-free)
__device__ __align__(16) uint32_t g_wbits[64 * 48]; // permuted fc1_w sign bits, row stride 48
__device__ unsigned long long     g_bconsP[64 * 4]; // [br*16+c]*4 = {q0,q0},{q1,q1},{q2,q2},{C,C}
__device__ __align__(16) float    g_fc2t[64 * 8];   // [j*8+0..4]=s_j*fc2_w col, [j*8+5]=T_j bits

// ---- packed f32x2 helpers (sm_103a) ---------------------------------------
__device__ __forceinline__ unsigned long long pack2(float lo, float hi) {
    unsigned long long r;
    asm("mov.b64 %0, {%1, %2};" : "=l"(r) : "r"(__float_as_uint(lo)), "r"(__float_as_uint(hi)));
    return r;
}
__device__ __forceinline__ unsigned long long fma2(unsigned long long a,
                                                   unsigned long long b,
                                                   unsigned long long c) {
    unsigned long long d;
    asm("fma.rn.f32x2 %0, %1, %2, %3;" : "=l"(d) : "l"(a), "l"(b), "l"(c));
    return d;
}

// ---------------------------------------------------------------------------
// Prep kernel: pack fc1 weight bits (permuted) + fold BN params.
// grid = 360 blocks * 256 thr = 2880 warps = 64 rows * 45 words (exact).
// ---------------------------------------------------------------------------
__global__ void prep_kernel(Ptrs p)
{
    const int t    = blockIdx.x * 256 + threadIdx.x;
    const int gw   = t >> 5;
    const int lane = t & 31;

    // ---- pack one 32-bit word of permuted fc1 weight sign bits per warp ----
    {
        const int j = gw / 45;       // fc1 output row
        const int w = gw - j * 45;   // feature word
        const int d = w * 32 + lane; // permuted bit index
        // d = OFF + 16*i + (15 - c)  ->  src = OFF + c*Lp + i
        int src;
        if (d < 176)      { int r = d;       src =       (15 - (r & 15)) * 11 + (r >> 4); }
        else if (d < 352) { int r = d - 176; src = 176 + (15 - (r & 15)) * 11 + (r >> 4); }
        else if (d < 704) { int r = d - 352; src = 352 + (15 - (r & 15)) * 22 + (r >> 4); }
        else              { int r = d - 704; src = 704 + (15 - (r & 15)) * 46 + (r >> 4); }
        const unsigned bal =
            __ballot_sync(0xffffffffu, p.fc1_w[j * 1440 + src] > 0.0f);
        if (lane == 0) g_wbits[j * 48 + w] = bal;
    }

    // ---- fold BN params (block 0 only) ----
    if (blockIdx.x == 0) {
        const int tid = threadIdx.x;
        if (tid < 64) {
            // FC1 BN with complemented features:
            //   val = inv*(2P' - 1440 - m1) + b1 = slope*P' + A,
            //   slope = 2*inv, A = b1 - inv*(1440 + p.m1)
            const float inv   = p.g1[tid] * rsqrtf(p.v1[tid] + EPSV);
            const float slope = 2.0f * inv;
            const float A     = p.b1[tid] - inv * (1440.0f + p.m1[tid]);
            float tthr = -A / slope;
            tthr = fmaxf(fminf(tthr, 2.0e9f), -2.0e9f);   // clamp before int cast
            int   T;
            float s;
            if (slope > 0.0f) { T = (int)floorf(tthr);        s =  1.0f; }
            else              { T = (int)ceilf(tthr) - 1;     s = -1.0f; }
            // FC2 transpose with s_j folded in; threshold bits in slot 5
            #pragma unroll
            for (int o = 0; o < 5; o++) g_fc2t[tid * 8 + o] = s * p.fc2_w[o * 64 + tid];
            g_fc2t[tid * 8 + 5] = __int_as_float(T);
            g_fc2t[tid * 8 + 6] = 0.0f;
            g_fc2t[tid * 8 + 7] = 0.0f;
        }
        if (tid >= 64 && tid < 128) {
            const int id = tid - 64;
            const int br = id >> 4, c = id & 15;
            const float* wc = p.w[br] + c * 3;   // (OUT_CH,1,K) row-major
            const float inv = p.g[br][c] * rsqrtf(p.v[br][c] + EPSV);
            float q[3];
            #pragma unroll
            for (int k = 0; k < 3; k++) {
                const float wk = wc[k];
                const float sg = (wk > 0.0f) ? 1.0f : ((wk < 0.0f) ? -1.0f : 0.0f);
                q[k] = inv * sg;
            }
            const float C = p.b[br][c] - inv * p.m[br][c];
            g_bconsP[id * 4 + 0] = pack2(q[0], q[0]);
            g_bconsP[id * 4 + 1] = pack2(q[1], q[1]);
            g_bconsP[id * 4 + 2] = pack2(q[2], q[2]);
            g_bconsP[id * 4 + 3] = pack2(C,    C);
        }
    }
}

// ---------------------------------------------------------------------------
// Main kernel: 64 samples per CTA, 1024 CTAs, 8 CTAs/SM (single wave).
// smem ~23.6KB/CTA -> 8*23.6 = 189KB <= 228KB; regs capped at 128 by
// __launch_bounds__(64, 8).
// ---------------------------------------------------------------------------
static constexpr int TPB     = 64;
static constexpr int XSTRIDE = 28;   // float4-aligned rows (112B); stride 28
                                     // is conflict-free for LDS.128 (offsets of
                                     // 8 consecutive threads mod 128B are distinct)

// Coalesced staging of x[s0+s][XB .. XB+XL) into smem tile (row stride 28).
// FULLY UNROLLED so ptxas front-batches the LDGs (MLP ~ XL).
template <int L, int XB, int XL>
__device__ __forceinline__ void load_chunk(float* s_x, const float* __restrict__ xg,
                                           int s0, int tid)
{
    #pragma unroll
    for (int k = 0; k < XL; k++) {
        const int idx  = tid + k * TPB;          // < TPB*XL
        const int s    = idx / XL;               // compile-time-const divisor
        const int pcol = idx - s * XL;
        s_x[s * XSTRIDE + pcol] = __ldg(&xg[(size_t)(s0 + s) * L + XB + pcol]);
    }
}

// Compute NP pooled positions starting at P0 of one branch using packed
// f32x2 FMAs: lanes (lo,hi) = (zA,zB) of one pooled pair.
// COMPLEMENT bit (1 = pooled max <= 0): u = lo&hi (LOP3), funnel-shift into mc.
// x values are fetched with LDS.128 from the (aligned) row, then packed.
template <int OFF, int XB, int P0, int NP>
__device__ __forceinline__ void proc_chunk(uint32_t f[45], const float* xrow,
                                           const unsigned long long* bcp)
{
    constexpr int A0 = 2 * P0 - XB;              // first float needed (>=0)
    constexpr int AL = A0 & ~3;                  // 16B-aligned start
    constexpr int NF = (A0 - AL) + 2 * NP + 2;   // floats to cover
    constexpr int NV = (NF + 3) / 4;             // float4 loads

    float4 xq[NV];
    const float4* x4 = reinterpret_cast<const float4*>(xrow);
    #pragma unroll
    for (int k = 0; k < NV; k++) xq[k] = x4[AL / 4 + k];
    const float* xvf = reinterpret_cast<const float*>(xq);  // const-indexed -> regs

    // overlapping packed pairs (x[2P0+i], x[2P0+i+1]) — invariant over channels
    unsigned long long xp[2 * NP + 1];
    #pragma unroll
    for (int i = 0; i < 2 * NP + 1; i++)
        xp[i] = pack2(xvf[A0 - AL + i], xvf[A0 - AL + i + 1]);

    uint32_t mc[NP];
    #pragma unroll
    for (int i = 0; i < NP; i++) mc[i] = 0u;

    #pragma unroll 2
    for (int c = 0; c < 16; c++) {
        // two LDS.128 (broadcast): {q0,q0},{q1,q1} and {q2,q2},{C,C}
        const ulonglong2 qa = *reinterpret_cast<const ulonglong2*>(bcp + 4 * c);
        const ulonglong2 qb = *reinterpret_cast<const ulonglong2*>(bcp + 4 * c + 2);
        #pragma unroll
        for (int ip = 0; ip < NP; ip++) {
            unsigned long long acc = fma2(qb.x, xp[2 * ip + 2], qb.y);
            acc = fma2(qa.y, xp[2 * ip + 1], acc);
            acc = fma2(qa.x, xp[2 * ip + 0], acc);
            const uint32_t u = (uint32_t)acc & (uint32_t)(acc >> 32);  // LOP3
            mc[ip] = __funnelshift_l(u, mc[ip], 1);                    // SHF
        }
    }
    #pragma unroll
    for (int ip = 0; ip < NP; ip++) {
        const int d = OFF + 16 * (P0 + ip);          // compile-time
        f[d >> 5] |= mc[ip] << (d & 31);             // shift is 0 or 16
    }
}

__global__ void __launch_bounds__(TPB, 8)
wavebnn_kernel(Ptrs p, float* __restrict__ out)
{
    __shared__ __align__(16) uint32_t s_wbits[64 * 48];
    __shared__ __align__(16) unsigned long long s_bconsP[64 * 4];
    __shared__ __align__(16) float s_fc2t[64 * 8];
    __shared__ __align__(16) float s_x[TPB * XSTRIDE];

    const int tid = threadIdx.x;
    const int s0  = blockIdx.x * TPB;

    // ---- stage constants with LDG.128 (fully unrolled, front-batched) ----
    {
        const uint4* gw4 = reinterpret_cast<const uint4*>(g_wbits);
        uint4*       sw4 = reinterpret_cast<uint4*>(s_wbits);
        #pragma unroll
        for (int k = 0; k < 12; k++) sw4[tid + k * TPB] = gw4[tid + k * TPB];
        const float4* gf4 = reinterpret_cast<const float4*>(g_fc2t);
        float4*       sf4 = reinterpret_cast<float4*>(s_fc2t);
        #pragma unroll
        for (int k = 0; k < 2; k++) sf4[tid + k * TPB] = gf4[tid + k * TPB];
        #pragma unroll
        for (int k = 0; k < 4; k++) s_bconsP[tid + k * TPB] = g_bconsP[tid + k * TPB];
    }
    // phase-1 x load overlaps the constant staging (same pre-barrier region)
    load_chunk<24, 0, 24>(s_x, p.x[0], s0, tid);

    uint32_t f[45];
    #pragma unroll
    for (int i = 0; i < 45; i++) f[i] = 0u;

    const float* xrow = &s_x[tid * XSTRIDE];

    // ---- phase 1: cA3 (L=24, Lp=11, OFF=0) ----
    __syncthreads();
    proc_chunk<0, 0, 0, 8>(f, xrow, s_bconsP + 0 * 64);
    proc_chunk<0, 0, 8, 3>(f, xrow, s_bconsP + 0 * 64);

    // ---- phase 2: cD3 (L=24, Lp=11, OFF=176) ----
    __syncthreads();
    load_chunk<24, 0, 24>(s_x, p.x[1], s0, tid);
    __syncthreads();
    proc_chunk<176, 0, 0, 8>(f, xrow, s_bconsP + 1 * 64);
    proc_chunk<176, 0, 8, 3>(f, xrow, s_bconsP + 1 * 64);

    // ---- phase 3: cD2 part 1 (L=47, OFF=352): cols [0,28), p=0..12 ----
    __syncthreads();
    load_chunk<47, 0, 28>(s_x, p.x[2], s0, tid);
    __syncthreads();
    proc_chunk<352, 0, 0, 8>(f, xrow, s_bconsP + 2 * 64);
    proc_chunk<352, 0, 8, 5>(f, xrow, s_bconsP + 2 * 64);

    // ---- phase 4: cD2 part 2: cols [24,47), p=13..21 ----
    __syncthreads();
    load_chunk<47, 24, 23>(s_x, p.x[2], s0, tid);
    __syncthreads();
    proc_chunk<352, 24, 13, 8>(f, xrow, s_bconsP + 2 * 64);
    proc_chunk<352, 24, 21, 1>(f, xrow, s_bconsP + 2 * 64);

    // ---- phase 5: cD1 part 1 (L=94, OFF=704): cols [0,28), p=0..12 ----
    __syncthreads();
    load_chunk<94, 0, 28>(s_x, p.x[3], s0, tid);
    __syncthreads();
    proc_chunk<704, 0, 0, 8>(f, xrow, s_bconsP + 3 * 64);
    proc_chunk<704, 0, 8, 5>(f, xrow, s_bconsP + 3 * 64);

    // ---- phase 6: cD1 part 2: cols [24,52), p=13..24 ----
    __syncthreads();
    load_chunk<94, 24, 28>(s_x, p.x[3], s0, tid);
    __syncthreads();
    proc_chunk<704, 24, 13, 8>(f, xrow, s_bconsP + 3 * 64);
    proc_chunk<704, 24, 21, 4>(f, xrow, s_bconsP + 3 * 64);

    // ---- phase 7: cD1 part 3: cols [48,76), p=25..36 ----
    __syncthreads();
    load_chunk<94, 48, 28>(s_x, p.x[3], s0, tid);
    __syncthreads();
    proc_chunk<704, 48, 25, 8>(f, xrow, s_bconsP + 3 * 64);
    proc_chunk<704, 48, 33, 4>(f, xrow, s_bconsP + 3 * 64);

    // ---- phase 8: cD1 part 4: cols [72,94), p=37..45 ----
    __syncthreads();
    load_chunk<94, 72, 22>(s_x, p.x[3], s0, tid);
    __syncthreads();
    proc_chunk<704, 72, 37, 8>(f, xrow, s_bconsP + 3 * 64);
    proc_chunk<704, 72, 45, 1>(f, xrow, s_bconsP + 3 * 64);

    // ---- FC1 (XOR/POPC, pairwise IADD3 accumulation) + threshold + FC2 ----
    float o0 = p.fc2_b[0], o1 = p.fc2_b[1], o2 = p.fc2_b[2],
          o3 = p.fc2_b[3], o4 = p.fc2_b[4];

    #pragma unroll 2
    for (int j = 0; j < 64; j++) {
        const uint32_t* wr = &s_wbits[j * 48];
        int a0 = 0, a1 = 0;
        #pragma unroll
        for (int w4 = 0; w4 < 11; w4++) {
            const uint4 ww = *reinterpret_cast<const uint4*>(wr + 4 * w4);
            a0 += __popc(f[4*w4+0] ^ ww.x) + __popc(f[4*w4+1] ^ ww.y);   // IADD3
            a1 += __popc(f[4*w4+2] ^ ww.z) + __popc(f[4*w4+3] ^ ww.w);   // IADD3
        }
        const int P = a0 + a1 + __popc(f[44] ^ wr[44]);                  // IADD3

        // two LDS.128: {w0..w3} and {w4, T_bits, 0, 0}
        const float4 wa = *reinterpret_cast<const float4*>(&s_fc2t[j * 8]);
        const float4 wb = *reinterpret_cast<const float4*>(&s_fc2t[j * 8 + 4]);
        const float  h  = (P > __float_as_int(wb.y)) ? 1.0f : -1.0f;  // ISETP+SEL

        o0 = fmaf(h, wa.x, o0);
        o1 = fmaf(h, wa.y, o1);
        o2 = fmaf(h, wa.z, o2);
        o3 = fmaf(h, wa.w, o3);
        o4 = fmaf(h, wb.x, o4);
    }

    const size_t ob = (size_t)(s0 + tid) * 5;
    out[ob + 0] = o0; out[ob + 1] = o1; out[ob + 2] = o2;
    out[ob + 3] = o3; out[ob + 4] = o4;
}

// ---------------------------------------------------------------------------
// Launch
// ---------------------------------------------------------------------------
extern "C" void kernel_launch(void* const* d_in, const int* in_sizes, int n_in,
                              void* d_out, int out_size)
{
    (void)n_in; (void)out_size;
    Ptrs p;
    // Disambiguate metadata ordering:
    //  dict order      : per branch [x,w,g,b,m,v]        -> in_sizes[1] == 48
    //  signature order : x*4 then per branch [w,g,b,m,v] -> in_sizes[1] == 65536*24
    const bool dict = (in_sizes[1] == 48);
    for (int br = 0; br < 4; br++) {
        if (dict) {
            p.x[br] = (const float*)d_in[br * 6 + 0];
            p.w[br] = (const float*)d_in[br * 6 + 1];
            p.g[br] = (const float*)d_in[br * 6 + 2];
            p.b[br] = (const float*)d_in[br * 6 + 3];
            p.m[br] = (const float*)d_in[br * 6 + 4];
            p.v[br] = (const float*)d_in[br * 6 + 5];
        } else {
            p.x[br] = (const float*)d_in[br];
            p.w[br] = (const float*)d_in[4 + br * 5 + 0];
            p.g[br] = (const float*)d_in[4 + br * 5 + 1];
            p.b[br] = (const float*)d_in[4 + br * 5 + 2];
            p.m[br] = (const float*)d_in[4 + br * 5 + 3];
            p.v[br] = (const float*)d_in[4 + br * 5 + 4];
        }
    }
    p.fc1_w = (const float*)d_in[24];
    p.g1    = (const float*)d_in[25];
    p.b1    = (const float*)d_in[26];
    p.m1    = (const float*)d_in[27];
    p.v1    = (const float*)d_in[28];
    p.fc2_w = (const float*)d_in[29];
    p.fc2_b = (const float*)d_in[30];

    prep_kernel<<<360, 256>>>(p);
    wavebnn_kernel<<<65536 / TPB, TPB>>>(p, (float*)d_out);
}

// round 9
// speedup vs baseline: 1.1425x; 1.1170x over previous
#include <cuda_runtime.h>
#include <cstdint>
#include <cstddef>

#define EPSV 1e-5f

// ---------------------------------------------------------------------------
// Problem constants
//   branches (order): cA3(L=24), cD3(L=24), cD2(L=47), cD1(L=94)
//   conv K=3, OUT_CH=16, POOL=2
//   Lp = {11,11,22,46}; global pooled-position index i: cA3 0-10, cD3 11-21,
//   cD2 22-43, cD1 44-89 (90 positions total).
//
// TWO-THREADS-PER-SAMPLE SPLIT: thread parity p in {0,1} handles channels
// c = 8p + c' (c'=0..7). Per-thread feature bits: d = 8*i + (7-c'), 720 bits
// = 23 words, stored COMPLEMENTED (1 = pooled max <= 0). Each parity has its
// own permuted fc1 weight table; full popcount P = P_self + shfl_xor(P,1);
// dot = 2P - 1440 folded into integer threshold T (h = P>T ? +1 : -1).
// FC2: even thread accumulates outputs 0-2, odd thread outputs 3-4.
// ---------------------------------------------------------------------------

struct Ptrs {
    const float* x[4];
    const float* w[4];
    const float* g[4];
    const float* b[4];
    const float* m[4];
    const float* v[4];
    const float* fc1_w;
    const float* g1; const float* b1; const float* m1; const float* v1;
    const float* fc2_w; const float* fc2_b;
};

// Precomputed parameter scratch (static device arrays: allocation-free)
__device__ __align__(16) uint32_t g_wbits[2 * 64 * 24]; // [p][j][w] permuted fc1 bits, row stride 24
__device__ unsigned long long     g_bconsP[64 * 4];     // [br*16+c]*4 = {q0,q0},{q1,q1},{q2,q2},{C,C}
__device__ __align__(16) float    g_fc2t[64 * 8];       // [j*8+ p*4 + k]: even {sw0,sw1,sw2,T}, odd {sw3,sw4,T,0}

// ---- packed f32x2 helpers (sm_103a) ---------------------------------------
__device__ __forceinline__ unsigned long long pack2(float lo, float hi) {
    unsigned long long r;
    asm("mov.b64 %0, {%1, %2};" : "=l"(r) : "r"(__float_as_uint(lo)), "r"(__float_as_uint(hi)));
    return r;
}
__device__ __forceinline__ unsigned long long fma2(unsigned long long a,
                                                   unsigned long long b,
                                                   unsigned long long c) {
    unsigned long long d;
    asm("fma.rn.f32x2 %0, %1, %2, %3;" : "=l"(d) : "l"(a), "l"(b), "l"(c));
    return d;
}

// ---------------------------------------------------------------------------
// Prep kernel: pack fc1 weight bits (per-parity permutation) + fold BN params.
// grid = 384 blocks * 256 thr = 3072 warps = 2 p * 64 rows * 24 words (exact).
// ---------------------------------------------------------------------------
__global__ void prep_kernel(Ptrs p)
{
    const int t    = blockIdx.x * 256 + threadIdx.x;
    const int gw   = t >> 5;
    const int lane = t & 31;

    // ---- pack one 32-bit word of permuted fc1 weight sign bits per warp ----
    {
        const int j   = gw / 48;         // fc1 output row
        const int rem = gw - j * 48;
        const int pp  = rem / 24;        // parity
        const int w   = rem - pp * 24;   // word within the 23-word (+1 pad) row
        const int d   = w * 32 + lane;   // per-thread bit index (0..767)
        const bool valid = (d < 720);
        int src = 0;
        if (valid) {
            const int i  = d >> 3;              // global pooled position 0..89
            const int cp = 7 - (d & 7);         // c'
            const int c  = 8 * pp + cp;         // reference channel
            int off, lp, ipos;
            if (i < 11)      { off = 0;   lp = 11; ipos = i; }
            else if (i < 22) { off = 176; lp = 11; ipos = i - 11; }
            else if (i < 44) { off = 352; lp = 22; ipos = i - 22; }
            else             { off = 704; lp = 46; ipos = i - 44; }
            src = off + c * lp + ipos;
        }
        const unsigned bal =
            __ballot_sync(0xffffffffu, valid && (p.fc1_w[j * 1440 + src] > 0.0f));
        if (lane == 0) g_wbits[(pp * 64 + j) * 24 + w] = bal;
    }

    // ---- fold BN params (block 0 only) ----
    if (blockIdx.x == 0) {
        const int tid = threadIdx.x;
        if (tid < 64) {
            // FC1 BN with complemented features:
            //   val = inv*(2P - 1440 - m1) + b1 = slope*P + A
            const float inv   = p.g1[tid] * rsqrtf(p.v1[tid] + EPSV);
            const float slope = 2.0f * inv;
            const float A     = p.b1[tid] - inv * (1440.0f + p.m1[tid]);
            float tthr = -A / slope;
            tthr = fmaxf(fminf(tthr, 2.0e9f), -2.0e9f);
            int   T;
            float s;
            if (slope > 0.0f) { T = (int)floorf(tthr);    s =  1.0f; }
            else              { T = (int)ceilf(tthr) - 1; s = -1.0f; }
            const float tb = __int_as_float(T);
            g_fc2t[tid * 8 + 0] = s * p.fc2_w[0 * 64 + tid];
            g_fc2t[tid * 8 + 1] = s * p.fc2_w[1 * 64 + tid];
            g_fc2t[tid * 8 + 2] = s * p.fc2_w[2 * 64 + tid];
            g_fc2t[tid * 8 + 3] = tb;
            g_fc2t[tid * 8 + 4] = s * p.fc2_w[3 * 64 + tid];
            g_fc2t[tid * 8 + 5] = s * p.fc2_w[4 * 64 + tid];
            g_fc2t[tid * 8 + 6] = tb;
            g_fc2t[tid * 8 + 7] = 0.0f;
        }
        if (tid >= 64 && tid < 128) {
            const int id = tid - 64;
            const int br = id >> 4, c = id & 15;
            const float* wc = p.w[br] + c * 3;   // (OUT_CH,1,K) row-major
            const float inv = p.g[br][c] * rsqrtf(p.v[br][c] + EPSV);
            float q[3];
            #pragma unroll
            for (int k = 0; k < 3; k++) {
                const float wk = wc[k];
                const float sg = (wk > 0.0f) ? 1.0f : ((wk < 0.0f) ? -1.0f : 0.0f);
                q[k] = inv * sg;
            }
            const float C = p.b[br][c] - inv * p.m[br][c];
            g_bconsP[id * 4 + 0] = pack2(q[0], q[0]);
            g_bconsP[id * 4 + 1] = pack2(q[1], q[1]);
            g_bconsP[id * 4 + 2] = pack2(q[2], q[2]);
            g_bconsP[id * 4 + 3] = pack2(C,    C);
        }
    }
}

// ---------------------------------------------------------------------------
// Main kernel: 128 threads = 64 samples per CTA (2 threads/sample),
// grid 1024 -> 131072 threads -> ~28 warps/SM resident (single wave).
// __launch_bounds__(128, 7): 73-reg cap, 7-CTA capacity (>= 6.92 avg).
// ---------------------------------------------------------------------------
static constexpr int TPB     = 128;
static constexpr int NSAMP   = 64;   // samples per CTA
static constexpr int XSTRIDE = 28;   // float4-aligned rows (112B)

// Coalesced staging of x[s0+s][XB .. XB+XL), s in [0,64), row stride 28.
template <int L, int XB, int XL>
__device__ __forceinline__ void load_chunk(float* s_x, const float* __restrict__ xg,
                                           int s0, int tid)
{
    constexpr int TOTAL = NSAMP * XL;
    constexpr int ITER  = (TOTAL + TPB - 1) / TPB;
    #pragma unroll
    for (int k = 0; k < ITER; k++) {
        const int idx = tid + k * TPB;
        if ((TOTAL % TPB == 0) || (idx < TOTAL)) {
            const int s    = idx / XL;
            const int pcol = idx - s * XL;
            s_x[s * XSTRIDE + pcol] = __ldg(&xg[(size_t)(s0 + s) * L + XB + pcol]);
        }
    }
}

// NP pooled positions (branch-local P0..), 8 channels (this thread's half).
// IBASE = global position base of the branch. Bits: d = 8*(IBASE+P0+ip),
// 8-bit group per position, byte-aligned (shift in {0,8,16,24}).
template <int IBASE, int XB, int P0, int NP>
__device__ __forceinline__ void proc_chunk(uint32_t f[23], const float* xrow,
                                           const unsigned long long* bcp)
{
    constexpr int A0 = 2 * P0 - XB;              // first float needed (>=0)
    constexpr int AL = A0 & ~3;                  // 16B-aligned start
    constexpr int NF = (A0 - AL) + 2 * NP + 2;
    constexpr int NV = (NF + 3) / 4;

    float4 xq[NV];
    const float4* x4 = reinterpret_cast<const float4*>(xrow);
    #pragma unroll
    for (int k = 0; k < NV; k++) xq[k] = x4[AL / 4 + k];
    const float* xvf = reinterpret_cast<const float*>(xq);

    unsigned long long xp[2 * NP + 1];
    #pragma unroll
    for (int i = 0; i < 2 * NP + 1; i++)
        xp[i] = pack2(xvf[A0 - AL + i], xvf[A0 - AL + i + 1]);

    uint32_t mc[NP];
    #pragma unroll
    for (int i = 0; i < NP; i++) mc[i] = 0u;

    #pragma unroll 2
    for (int c = 0; c < 8; c++) {   // this thread's 8 channels
        const ulonglong2 qa = *reinterpret_cast<const ulonglong2*>(bcp + 4 * c);
        const ulonglong2 qb = *reinterpret_cast<const ulonglong2*>(bcp + 4 * c + 2);
        #pragma unroll
        for (int ip = 0; ip < NP; ip++) {
            unsigned long long acc = fma2(qb.x, xp[2 * ip + 2], qb.y);
            acc = fma2(qa.y, xp[2 * ip + 1], acc);
            acc = fma2(qa.x, xp[2 * ip + 0], acc);
            const uint32_t u = (uint32_t)acc & (uint32_t)(acc >> 32);  // LOP3
            mc[ip] = __funnelshift_l(u, mc[ip], 1);                    // SHF
        }
    }
    #pragma unroll
    for (int ip = 0; ip < NP; ip++) {
        const int d = 8 * (IBASE + P0 + ip);     // compile-time
        f[d >> 5] |= mc[ip] << (d & 31);         // shift in {0,8,16,24}
    }
}

__global__ void __launch_bounds__(TPB, 7)
wavebnn_kernel(Ptrs p, float* __restrict__ out)
{
    __shared__ __align__(16) uint32_t s_wbits[2 * 64 * 24];
    __shared__ __align__(16) unsigned long long s_bconsP[64 * 4];
    __shared__ __align__(16) float s_fc2t[64 * 8];
    __shared__ __align__(16) float s_x[NSAMP * XSTRIDE];

    const int tid    = threadIdx.x;
    const int parity = tid & 1;
    const int samp   = tid >> 1;               // sample row within CTA
    const int s0     = blockIdx.x * NSAMP;

    // ---- stage constants (fully unrolled, front-batched) ----
    {
        const uint4* gw4 = reinterpret_cast<const uint4*>(g_wbits);
        uint4*       sw4 = reinterpret_cast<uint4*>(s_wbits);
        #pragma unroll
        for (int k = 0; k < 6; k++) sw4[tid + k * TPB] = gw4[tid + k * TPB];
        reinterpret_cast<float4*>(s_fc2t)[tid] =
            reinterpret_cast<const float4*>(g_fc2t)[tid];
        #pragma unroll
        for (int k = 0; k < 2; k++) s_bconsP[tid + k * TPB] = g_bconsP[tid + k * TPB];
    }
    // phase-1 x load overlaps the constant staging
    load_chunk<24, 0, 24>(s_x, p.x[0], s0, tid);

    uint32_t f[23];
    #pragma unroll
    for (int i = 0; i < 23; i++) f[i] = 0u;

    const float* xrow = &s_x[samp * XSTRIDE];
    const unsigned long long* bc0 = s_bconsP + parity * 32;  // +8 channels * 4

    // ---- phase 1: cA3 (Lp=11, IBASE=0) ----
    __syncthreads();
    proc_chunk<0, 0, 0, 6>(f, xrow, bc0 + 0 * 64);
    proc_chunk<0, 0, 6, 5>(f, xrow, bc0 + 0 * 64);

    // ---- phase 2: cD3 (Lp=11, IBASE=11) ----
    __syncthreads();
    load_chunk<24, 0, 24>(s_x, p.x[1], s0, tid);
    __syncthreads();
    proc_chunk<11, 0, 0, 6>(f, xrow, bc0 + 1 * 64);
    proc_chunk<11, 0, 6, 5>(f, xrow, bc0 + 1 * 64);

    // ---- phase 3: cD2 part 1 (L=47, IBASE=22): cols [0,28), p=0..12 ----
    __syncthreads();
    load_chunk<47, 0, 28>(s_x, p.x[2], s0, tid);
    __syncthreads();
    proc_chunk<22, 0, 0, 7>(f, xrow, bc0 + 2 * 64);
    proc_chunk<22, 0, 7, 6>(f, xrow, bc0 + 2 * 64);

    // ---- phase 4: cD2 part 2: cols [24,47), p=13..21 ----
    __syncthreads();
    load_chunk<47, 24, 23>(s_x, p.x[2], s0, tid);
    __syncthreads();
    proc_chunk<22, 24, 13, 5>(f, xrow, bc0 + 2 * 64);
    proc_chunk<22, 24, 18, 4>(f, xrow, bc0 + 2 * 64);

    // ---- phase 5: cD1 part 1 (L=94, IBASE=44): cols [0,28), p=0..12 ----
    __syncthreads();
    load_chunk<94, 0, 28>(s_x, p.x[3], s0, tid);
    __syncthreads();
    proc_chunk<44, 0, 0, 7>(f, xrow, bc0 + 3 * 64);
    proc_chunk<44, 0, 7, 6>(f, xrow, bc0 + 3 * 64);

    // ---- phase 6: cD1 part 2: cols [24,52), p=13..24 ----
    __syncthreads();
    load_chunk<94, 24, 28>(s_x, p.x[3], s0, tid);
    __syncthreads();
    proc_chunk<44, 24, 13, 6>(f, xrow, bc0 + 3 * 64);
    proc_chunk<44, 24, 19, 6>(f, xrow, bc0 + 3 * 64);

    // ---- phase 7: cD1 part 3: cols [48,76), p=25..36 ----
    __syncthreads();
    load_chunk<94, 48, 28>(s_x, p.x[3], s0, tid);
    __syncthreads();
    proc_chunk<44, 48, 25, 6>(f, xrow, bc0 + 3 * 64);
    proc_chunk<44, 48, 31, 6>(f, xrow, bc0 + 3 * 64);

    // ---- phase 8: cD1 part 4: cols [72,94), p=37..45 ----
    __syncthreads();
    load_chunk<94, 72, 22>(s_x, p.x[3], s0, tid);
    __syncthreads();
    proc_chunk<44, 72, 37, 5>(f, xrow, bc0 + 3 * 64);
    proc_chunk<44, 72, 42, 4>(f, xrow, bc0 + 3 * 64);

    // ---- FC1 (half popc + pair-SHFL merge) + threshold + split FC2 ----
    float o0, o1, o2;
    if (parity == 0) { o0 = p.fc2_b[0]; o1 = p.fc2_b[1]; o2 = p.fc2_b[2]; }
    else             { o0 = p.fc2_b[3]; o1 = p.fc2_b[4]; o2 = 0.0f; }

    const uint32_t* wtab = &s_wbits[parity * 64 * 24];

    #pragma unroll 2
    for (int j = 0; j < 64; j++) {
        const uint32_t* wr = &wtab[j * 24];
        int a0 = 0, a1 = 0;
        #pragma unroll
        for (int w4 = 0; w4 < 5; w4++) {
            const uint4 ww = *reinterpret_cast<const uint4*>(wr + 4 * w4);
            a0 += __popc(f[4*w4+0] ^ ww.x) + __popc(f[4*w4+1] ^ ww.y);   // IADD3
            a1 += __popc(f[4*w4+2] ^ ww.z) + __popc(f[4*w4+3] ^ ww.w);   // IADD3
        }
        a0 += __popc(f[20] ^ wr[20]) + __popc(f[21] ^ wr[21]);
        a1 += __popc(f[22] ^ wr[22]);
        const int Ph = a0 + a1;
        const int P  = Ph + __shfl_xor_sync(0xffffffffu, Ph, 1);  // pair merge

        const float4 wv = *reinterpret_cast<const float4*>(&s_fc2t[j * 8 + parity * 4]);
        const int    T  = __float_as_int(parity ? wv.z : wv.w);
        const float  h  = (P > T) ? 1.0f : -1.0f;                 // ISETP+SEL

        o0 = fmaf(h, wv.x, o0);
        o1 = fmaf(h, wv.y, o1);
        if (parity == 0) o2 = fmaf(h, wv.z, o2);   // predicated FFMA
    }

    const size_t ob = (size_t)(s0 + samp) * 5 + parity * 3;
    out[ob + 0] = o0;
    out[ob + 1] = o1;
    if (parity == 0) out[ob + 2] = o2;
}

// ---------------------------------------------------------------------------
// Launch
// ---------------------------------------------------------------------------
extern "C" void kernel_launch(void* const* d_in, const int* in_sizes, int n_in,
                              void* d_out, int out_size)
{
    (void)n_in; (void)out_size;
    Ptrs p;
    // Disambiguate metadata ordering:
    //  dict order      : per branch [x,w,g,b,m,v]        -> in_sizes[1] == 48
    //  signature order : x*4 then per branch [w,g,b,m,v] -> in_sizes[1] == 65536*24
    const bool dict = (in_sizes[1] == 48);
    for (int br = 0; br < 4; br++) {
        if (dict) {
            p.x[br] = (const float*)d_in[br * 6 + 0];
            p.w[br] = (const float*)d_in[br * 6 + 1];
            p.g[br] = (const float*)d_in[br * 6 + 2];
            p.b[br] = (const float*)d_in[br * 6 + 3];
            p.m[br] = (const float*)d_in[br * 6 + 4];
            p.v[br] = (const float*)d_in[br * 6 + 5];
        } else {
            p.x[br] = (const float*)d_in[br];
            p.w[br] = (const float*)d_in[4 + br * 5 + 0];
            p.g[br] = (const float*)d_in[4 + br * 5 + 1];
            p.b[br] = (const float*)d_in[4 + br * 5 + 2];
            p.m[br] = (const float*)d_in[4 + br * 5 + 3];
            p.v[br] = (const float*)d_in[4 + br * 5 + 4];
        }
    }
    p.fc1_w = (const float*)d_in[24];
    p.g1    = (const float*)d_in[25];
    p.b1    = (const float*)d_in[26];
    p.m1    = (const float*)d_in[27];
    p.v1    = (const float*)d_in[28];
    p.fc2_w = (const float*)d_in[29];
    p.fc2_b = (const float*)d_in[30];

    prep_kernel<<<384, 256>>>(p);
    wavebnn_kernel<<<65536 / NSAMP, TPB>>>(p, (float*)d_out);
}

// round 10
// speedup vs baseline: 1.1880x; 1.0399x over previous
#include <cuda_runtime.h>
#include <cstdint>
#include <cstddef>

#define EPSV 1e-5f

// ---------------------------------------------------------------------------
// Problem constants
//   branches (order): cA3(L=24), cD3(L=24), cD2(L=47), cD1(L=94)
//   conv K=3, OUT_CH=16, POOL=2
//   Lp = {11,11,22,46}; global pooled-position index i: cA3 0-10, cD3 11-21,
//   cD2 22-43, cD1 44-89 (90 positions total).
//
// TWO-THREADS-PER-SAMPLE SPLIT: thread parity p in {0,1} handles channels
// c = 8p + c' (c'=0..7). Per-thread feature bits: d = 8*i + (7-c'), 720 bits
// = 23 words, stored COMPLEMENTED (1 = pooled max <= 0). Each parity has its
// own permuted fc1 weight table; full popcount P = P_self + shfl_xor(P,1);
// dot = 2P - 1440 folded into integer threshold T (h = P>T ? +1 : -1).
// FC2: even thread accumulates outputs 0-2, odd thread outputs 3-4.
// ---------------------------------------------------------------------------

struct Ptrs {
    const float* x[4];
    const float* w[4];
    const float* g[4];
    const float* b[4];
    const float* m[4];
    const float* v[4];
    const float* fc1_w;
    const float* g1; const float* b1; const float* m1; const float* v1;
    const float* fc2_w; const float* fc2_b;
};

// Precomputed parameter scratch (static device arrays: allocation-free)
__device__ __align__(16) uint32_t g_wbits[2 * 64 * 24]; // [p][j][w] permuted fc1 bits, row stride 24
__device__ unsigned long long     g_bconsP[64 * 4];     // [br*16+c]*4 = {q0,q0},{q1,q1},{q2,q2},{C,C}
__device__ __align__(16) float    g_fc2t[64 * 8];       // [j*8+ p*4 + k]: even {sw0,sw1,sw2,T}, odd {sw3,sw4,T,0}

// ---- packed f32x2 helpers (sm_103a) ---------------------------------------
__device__ __forceinline__ unsigned long long pack2(float lo, float hi) {
    unsigned long long r;
    asm("mov.b64 %0, {%1, %2};" : "=l"(r) : "r"(__float_as_uint(lo)), "r"(__float_as_uint(hi)));
    return r;
}
__device__ __forceinline__ unsigned long long fma2(unsigned long long a,
                                                   unsigned long long b,
                                                   unsigned long long c) {
    unsigned long long d;
    asm("fma.rn.f32x2 %0, %1, %2, %3;" : "=l"(d) : "l"(a), "l"(b), "l"(c));
    return d;
}

// ---------------------------------------------------------------------------
// Prep kernel: pack fc1 weight bits (per-parity permutation) + fold BN params.
// grid = 384 blocks * 256 thr = 3072 warps = 2 p * 64 rows * 24 words (exact).
// ---------------------------------------------------------------------------
__global__ void prep_kernel(Ptrs p)
{
    const int t    = blockIdx.x * 256 + threadIdx.x;
    const int gw   = t >> 5;
    const int lane = t & 31;

    // ---- pack one 32-bit word of permuted fc1 weight sign bits per warp ----
    {
        const int j   = gw / 48;         // fc1 output row
        const int rem = gw - j * 48;
        const int pp  = rem / 24;        // parity
        const int w   = rem - pp * 24;   // word within the 23-word (+1 pad) row
        const int d   = w * 32 + lane;   // per-thread bit index (0..767)
        const bool valid = (d < 720);
        int src = 0;
        if (valid) {
            const int i  = d >> 3;              // global pooled position 0..89
            const int cp = 7 - (d & 7);         // c'
            const int c  = 8 * pp + cp;         // reference channel
            int off, lp, ipos;
            if (i < 11)      { off = 0;   lp = 11; ipos = i; }
            else if (i < 22) { off = 176; lp = 11; ipos = i - 11; }
            else if (i < 44) { off = 352; lp = 22; ipos = i - 22; }
            else             { off = 704; lp = 46; ipos = i - 44; }
            src = off + c * lp + ipos;
        }
        const unsigned bal =
            __ballot_sync(0xffffffffu, valid && (p.fc1_w[j * 1440 + src] > 0.0f));
        if (lane == 0) g_wbits[(pp * 64 + j) * 24 + w] = bal;
    }

    // ---- fold BN params (block 0 only) ----
    if (blockIdx.x == 0) {
        const int tid = threadIdx.x;
        if (tid < 64) {
            // FC1 BN with complemented features:
            //   val = inv*(2P - 1440 - m1) + b1 = slope*P + A
            const float inv   = p.g1[tid] * rsqrtf(p.v1[tid] + EPSV);
            const float slope = 2.0f * inv;
            const float A     = p.b1[tid] - inv * (1440.0f + p.m1[tid]);
            float tthr = -A / slope;
            tthr = fmaxf(fminf(tthr, 2.0e9f), -2.0e9f);
            int   T;
            float s;
            if (slope > 0.0f) { T = (int)floorf(tthr);    s =  1.0f; }
            else              { T = (int)ceilf(tthr) - 1; s = -1.0f; }
            const float tb = __int_as_float(T);
            g_fc2t[tid * 8 + 0] = s * p.fc2_w[0 * 64 + tid];
            g_fc2t[tid * 8 + 1] = s * p.fc2_w[1 * 64 + tid];
            g_fc2t[tid * 8 + 2] = s * p.fc2_w[2 * 64 + tid];
            g_fc2t[tid * 8 + 3] = tb;
            g_fc2t[tid * 8 + 4] = s * p.fc2_w[3 * 64 + tid];
            g_fc2t[tid * 8 + 5] = s * p.fc2_w[4 * 64 + tid];
            g_fc2t[tid * 8 + 6] = tb;
            g_fc2t[tid * 8 + 7] = 0.0f;
        }
        if (tid >= 64 && tid < 128) {
            const int id = tid - 64;
            const int br = id >> 4, c = id & 15;
            const float* wc = p.w[br] + c * 3;   // (OUT_CH,1,K) row-major
            const float inv = p.g[br][c] * rsqrtf(p.v[br][c] + EPSV);
            float q[3];
            #pragma unroll
            for (int k = 0; k < 3; k++) {
                const float wk = wc[k];
                const float sg = (wk > 0.0f) ? 1.0f : ((wk < 0.0f) ? -1.0f : 0.0f);
                q[k] = inv * sg;
            }
            const float C = p.b[br][c] - inv * p.m[br][c];
            g_bconsP[id * 4 + 0] = pack2(q[0], q[0]);
            g_bconsP[id * 4 + 1] = pack2(q[1], q[1]);
            g_bconsP[id * 4 + 2] = pack2(q[2], q[2]);
            g_bconsP[id * 4 + 3] = pack2(C,    C);
        }
    }
}

// ---------------------------------------------------------------------------
// Main kernel: 128 threads = 64 samples per CTA (2 threads/sample),
// grid 1024 -> 131072 threads -> ~28 warps/SM resident (single wave).
// __launch_bounds__(128, 7): 73-reg cap. smem ~30.6KB * 7 = 214KB <= 228KB.
// Double-buffered x tile: next phase's global loads issue before current
// phase's compute -> LDG latency hidden; 8 barriers total (was 15).
// ---------------------------------------------------------------------------
static constexpr int TPB     = 128;
static constexpr int NSAMP   = 64;   // samples per CTA
static constexpr int XSTRIDE = 28;   // float4-aligned rows (112B)

// Coalesced staging of x[s0+s][XB .. XB+XL), s in [0,64), row stride 28.
template <int L, int XB, int XL>
__device__ __forceinline__ void load_chunk(float* s_x, const float* __restrict__ xg,
                                           int s0, int tid)
{
    constexpr int TOTAL = NSAMP * XL;
    constexpr int ITER  = (TOTAL + TPB - 1) / TPB;
    #pragma unroll
    for (int k = 0; k < ITER; k++) {
        const int idx = tid + k * TPB;
        if ((TOTAL % TPB == 0) || (idx < TOTAL)) {
            const int s    = idx / XL;
            const int pcol = idx - s * XL;
            s_x[s * XSTRIDE + pcol] = __ldg(&xg[(size_t)(s0 + s) * L + XB + pcol]);
        }
    }
}

// NP pooled positions (branch-local P0..), 8 channels (this thread's half).
// IBASE = global position base of the branch. Bits: d = 8*(IBASE+P0+ip),
// 8-bit group per position, byte-aligned (shift in {0,8,16,24}).
template <int IBASE, int XB, int P0, int NP>
__device__ __forceinline__ void proc_chunk(uint32_t f[23], const float* xrow,
                                           const unsigned long long* bcp)
{
    constexpr int A0 = 2 * P0 - XB;              // first float needed (>=0)
    constexpr int AL = A0 & ~3;                  // 16B-aligned start
    constexpr int NF = (A0 - AL) + 2 * NP + 2;
    constexpr int NV = (NF + 3) / 4;

    float4 xq[NV];
    const float4* x4 = reinterpret_cast<const float4*>(xrow);
    #pragma unroll
    for (int k = 0; k < NV; k++) xq[k] = x4[AL / 4 + k];
    const float* xvf = reinterpret_cast<const float*>(xq);

    unsigned long long xp[2 * NP + 1];
    #pragma unroll
    for (int i = 0; i < 2 * NP + 1; i++)
        xp[i] = pack2(xvf[A0 - AL + i], xvf[A0 - AL + i + 1]);

    uint32_t mc[NP];
    #pragma unroll
    for (int i = 0; i < NP; i++) mc[i] = 0u;

    #pragma unroll 2
    for (int c = 0; c < 8; c++) {   // this thread's 8 channels
        const ulonglong2 qa = *reinterpret_cast<const ulonglong2*>(bcp + 4 * c);
        const ulonglong2 qb = *reinterpret_cast<const ulonglong2*>(bcp + 4 * c + 2);
        #pragma unroll
        for (int ip = 0; ip < NP; ip++) {
            unsigned long long acc = fma2(qb.x, xp[2 * ip + 2], qb.y);
            acc = fma2(qa.y, xp[2 * ip + 1], acc);
            acc = fma2(qa.x, xp[2 * ip + 0], acc);
            const uint32_t u = (uint32_t)acc & (uint32_t)(acc >> 32);  // LOP3
            mc[ip] = __funnelshift_l(u, mc[ip], 1);                    // SHF
        }
    }
    #pragma unroll
    for (int ip = 0; ip < NP; ip++) {
        const int d = 8 * (IBASE + P0 + ip);     // compile-time
        f[d >> 5] |= mc[ip] << (d & 31);         // shift in {0,8,16,24}
    }
}

__global__ void __launch_bounds__(TPB, 7)
wavebnn_kernel(Ptrs p, float* __restrict__ out)
{
    __shared__ __align__(16) uint32_t s_wbits[2 * 64 * 24];
    __shared__ __align__(16) unsigned long long s_bconsP[64 * 4];
    __shared__ __align__(16) float s_fc2t[64 * 8];
    __shared__ __align__(16) float s_x[2][NSAMP * XSTRIDE];

    const int tid    = threadIdx.x;
    const int parity = tid & 1;
    const int samp   = tid >> 1;               // sample row within CTA
    const int s0     = blockIdx.x * NSAMP;

    // ---- stage constants (fully unrolled, front-batched) ----
    {
        const uint4* gw4 = reinterpret_cast<const uint4*>(g_wbits);
        uint4*       sw4 = reinterpret_cast<uint4*>(s_wbits);
        #pragma unroll
        for (int k = 0; k < 6; k++) sw4[tid + k * TPB] = gw4[tid + k * TPB];
        reinterpret_cast<float4*>(s_fc2t)[tid] =
            reinterpret_cast<const float4*>(g_fc2t)[tid];
        #pragma unroll
        for (int k = 0; k < 2; k++) s_bconsP[tid + k * TPB] = g_bconsP[tid + k * TPB];
    }
    // phase-1 x load overlaps the constant staging
    load_chunk<24, 0, 24>(s_x[0], p.x[0], s0, tid);

    uint32_t f[23];
    #pragma unroll
    for (int i = 0; i < 23; i++) f[i] = 0u;

    const float* xrow0 = &s_x[0][samp * XSTRIDE];
    const float* xrow1 = &s_x[1][samp * XSTRIDE];
    const unsigned long long* bc0 = s_bconsP + parity * 32;  // +8 channels * 4

    // ---- phase 1: cA3 (Lp=11, IBASE=0) [buf0]; prefetch cD3 -> buf1 ----
    __syncthreads();
    load_chunk<24, 0, 24>(s_x[1], p.x[1], s0, tid);
    proc_chunk<0, 0, 0, 6>(f, xrow0, bc0 + 0 * 64);
    proc_chunk<0, 0, 6, 5>(f, xrow0, bc0 + 0 * 64);

    // ---- phase 2: cD3 (IBASE=11) [buf1]; prefetch cD2[0,28) -> buf0 ----
    __syncthreads();
    load_chunk<47, 0, 28>(s_x[0], p.x[2], s0, tid);
    proc_chunk<11, 0, 0, 6>(f, xrow1, bc0 + 1 * 64);
    proc_chunk<11, 0, 6, 5>(f, xrow1, bc0 + 1 * 64);

    // ---- phase 3: cD2 p1 (IBASE=22, p=0..12) [buf0]; prefetch cD2[24,47) ----
    __syncthreads();
    load_chunk<47, 24, 23>(s_x[1], p.x[2], s0, tid);
    proc_chunk<22, 0, 0, 7>(f, xrow0, bc0 + 2 * 64);
    proc_chunk<22, 0, 7, 6>(f, xrow0, bc0 + 2 * 64);

    // ---- phase 4: cD2 p2 (p=13..21) [buf1]; prefetch cD1[0,28) -> buf0 ----
    __syncthreads();
    load_chunk<94, 0, 28>(s_x[0], p.x[3], s0, tid);
    proc_chunk<22, 24, 13, 5>(f, xrow1, bc0 + 2 * 64);
    proc_chunk<22, 24, 18, 4>(f, xrow1, bc0 + 2 * 64);

    // ---- phase 5: cD1 p1 (IBASE=44, p=0..12) [buf0]; prefetch cD1[24,52) ----
    __syncthreads();
    load_chunk<94, 24, 28>(s_x[1], p.x[3], s0, tid);
    proc_chunk<44, 0, 0, 7>(f, xrow0, bc0 + 3 * 64);
    proc_chunk<44, 0, 7, 6>(f, xrow0, bc0 + 3 * 64);

    // ---- phase 6: cD1 p2 (p=13..24) [buf1]; prefetch cD1[48,76) -> buf0 ----
    __syncthreads();
    load_chunk<94, 48, 28>(s_x[0], p.x[3], s0, tid);
    proc_chunk<44, 24, 13, 6>(f, xrow1, bc0 + 3 * 64);
    proc_chunk<44, 24, 19, 6>(f, xrow1, bc0 + 3 * 64);

    // ---- phase 7: cD1 p3 (p=25..36) [buf0]; prefetch cD1[72,94) -> buf1 ----
    __syncthreads();
    load_chunk<94, 72, 22>(s_x[1], p.x[3], s0, tid);
    proc_chunk<44, 48, 25, 6>(f, xrow0, bc0 + 3 * 64);
    proc_chunk<44, 48, 31, 6>(f, xrow0, bc0 + 3 * 64);

    // ---- phase 8: cD1 p4 (p=37..45) [buf1] ----
    __syncthreads();
    proc_chunk<44, 72, 37, 5>(f, xrow1, bc0 + 3 * 64);
    proc_chunk<44, 72, 42, 4>(f, xrow1, bc0 + 3 * 64);

    // ---- FC1: 4-row batches (4 independent popc trees -> 4 pipelined SHFLs)
    float o0, o1, o2;
    if (parity == 0) { o0 = p.fc2_b[0]; o1 = p.fc2_b[1]; o2 = p.fc2_b[2]; }
    else             { o0 = p.fc2_b[3]; o1 = p.fc2_b[4]; o2 = 0.0f; }

    const uint32_t* wtab = &s_wbits[parity * 64 * 24];

    #pragma unroll 1
    for (int j4 = 0; j4 < 64; j4 += 4) {
        int Pm[4];
        #pragma unroll
        for (int u = 0; u < 4; u++) {
            const uint32_t* wr = &wtab[(j4 + u) * 24];
            int a0 = 0, a1 = 0;
            #pragma unroll
            for (int w4 = 0; w4 < 5; w4++) {
                const uint4 ww = *reinterpret_cast<const uint4*>(wr + 4 * w4);
                a0 += __popc(f[4*w4+0] ^ ww.x) + __popc(f[4*w4+1] ^ ww.y);   // IADD3
                a1 += __popc(f[4*w4+2] ^ ww.z) + __popc(f[4*w4+3] ^ ww.w);   // IADD3
            }
            a0 += __popc(f[20] ^ wr[20]) + __popc(f[21] ^ wr[21]);
            a1 += __popc(f[22] ^ wr[22]);
            Pm[u] = a0 + a1;
        }
        #pragma unroll
        for (int u = 0; u < 4; u++)
            Pm[u] += __shfl_xor_sync(0xffffffffu, Pm[u], 1);  // pair merge x4
        #pragma unroll
        for (int u = 0; u < 4; u++) {
            const float4 wv =
                *reinterpret_cast<const float4*>(&s_fc2t[(j4 + u) * 8 + parity * 4]);
            const int   T = __float_as_int(parity ? wv.z : wv.w);
            const float h = (Pm[u] > T) ? 1.0f : -1.0f;        // ISETP+SEL
            o0 = fmaf(h, wv.x, o0);
            o1 = fmaf(h, wv.y, o1);
            if (parity == 0) o2 = fmaf(h, wv.z, o2);           // predicated FFMA
        }
    }

    const size_t ob = (size_t)(s0 + samp) * 5 + parity * 3;
    out[ob + 0] = o0;
    out[ob + 1] = o1;
    if (parity == 0) out[ob + 2] = o2;
}

// ---------------------------------------------------------------------------
// Launch
// ---------------------------------------------------------------------------
extern "C" void kernel_launch(void* const* d_in, const int* in_sizes, int n_in,
                              void* d_out, int out_size)
{
    (void)n_in; (void)out_size;
    Ptrs p;
    // Disambiguate metadata ordering:
    //  dict order      : per branch [x,w,g,b,m,v]        -> in_sizes[1] == 48
    //  signature order : x*4 then per branch [w,g,b,m,v] -> in_sizes[1] == 65536*24
    const bool dict = (in_sizes[1] == 48);
    for (int br = 0; br < 4; br++) {
        if (dict) {
            p.x[br] = (const float*)d_in[br * 6 + 0];
            p.w[br] = (const float*)d_in[br * 6 + 1];
            p.g[br] = (const float*)d_in[br * 6 + 2];
            p.b[br] = (const float*)d_in[br * 6 + 3];
            p.m[br] = (const float*)d_in[br * 6 + 4];
            p.v[br] = (const float*)d_in[br * 6 + 5];
        } else {
            p.x[br] = (const float*)d_in[br];
            p.w[br] = (const float*)d_in[4 + br * 5 + 0];
            p.g[br] = (const float*)d_in[4 + br * 5 + 1];
            p.b[br] = (const float*)d_in[4 + br * 5 + 2];
            p.m[br] = (const float*)d_in[4 + br * 5 + 3];
            p.v[br] = (const float*)d_in[4 + br * 5 + 4];
        }
    }
    p.fc1_w = (const float*)d_in[24];
    p.g1    = (const float*)d_in[25];
    p.b1    = (const float*)d_in[26];
    p.m1    = (const float*)d_in[27];
    p.v1    = (const float*)d_in[28];
    p.fc2_w = (const float*)d_in[29];
    p.fc2_b = (const float*)d_in[30];

    prep_kernel<<<384, 256>>>(p);
    wavebnn_kernel<<<65536 / NSAMP, TPB>>>(p, (float*)d_out);
}

// round 11
// speedup vs baseline: 1.2208x; 1.0276x over previous
#include <cuda_runtime.h>
#include <cstdint>
#include <cstddef>

#define EPSV 1e-5f

// ---------------------------------------------------------------------------
// Problem constants
//   branches (order): cA3(L=24), cD3(L=24), cD2(L=47), cD1(L=94)
//   conv K=3, OUT_CH=16, POOL=2
//   Lp = {11,11,22,46}; global pooled-position index i: cA3 0-10, cD3 11-21,
//   cD2 22-43, cD1 44-89 (90 positions total).
//
// TWO-THREADS-PER-SAMPLE SPLIT: thread parity p in {0,1} handles channels
// c = 8p + c' (c'=0..7). Per-thread feature bits: d = 8*i + (7-c'), 720 bits
// = 23 words, stored COMPLEMENTED (1 = pooled max <= 0). Each parity has its
// own permuted fc1 weight table; full popcount P = P_self + shfl_xor(P,1);
// dot = 2P - 1440 folded into integer threshold T (h = P>T ? +1 : -1).
// FC2: even thread accumulates outputs 0-2, odd thread outputs 3-4.
// ---------------------------------------------------------------------------

struct Ptrs {
    const float* x[4];
    const float* w[4];
    const float* g[4];
    const float* b[4];
    const float* m[4];
    const float* v[4];
    const float* fc1_w;
    const float* g1; const float* b1; const float* m1; const float* v1;
    const float* fc2_w; const float* fc2_b;
};

// Precomputed parameter scratch (static device arrays: allocation-free)
__device__ __align__(16) uint32_t g_wbits[2 * 64 * 24]; // [p][j][w] permuted fc1 bits, row stride 24
__device__ unsigned long long     g_bconsP[64 * 4];     // [br*16+c]*4 = {q0,q0},{q1,q1},{q2,q2},{C,C}
__device__ __align__(16) float    g_fc2t[64 * 8];       // [j*8+ p*4 + k]: even {sw0,sw1,sw2,T}, odd {sw3,sw4,T,0}

// ---- packed f32x2 helpers (sm_103a) ---------------------------------------
__device__ __forceinline__ unsigned long long pack2(float lo, float hi) {
    unsigned long long r;
    asm("mov.b64 %0, {%1, %2};" : "=l"(r) : "r"(__float_as_uint(lo)), "r"(__float_as_uint(hi)));
    return r;
}
__device__ __forceinline__ unsigned long long fma2(unsigned long long a,
                                                   unsigned long long b,
                                                   unsigned long long c) {
    unsigned long long d;
    asm("fma.rn.f32x2 %0, %1, %2, %3;" : "=l"(d) : "l"(a), "l"(b), "l"(c));
    return d;
}

// ---------------------------------------------------------------------------
// Prep kernel: pack fc1 weight bits (per-parity permutation) + fold BN params.
// grid = 384 blocks * 256 thr = 3072 warps = 2 p * 64 rows * 24 words (exact).
// ---------------------------------------------------------------------------
__global__ void prep_kernel(Ptrs p)
{
    const int t    = blockIdx.x * 256 + threadIdx.x;
    const int gw   = t >> 5;
    const int lane = t & 31;

    // ---- pack one 32-bit word of permuted fc1 weight sign bits per warp ----
    {
        const int j   = gw / 48;         // fc1 output row
        const int rem = gw - j * 48;
        const int pp  = rem / 24;        // parity
        const int w   = rem - pp * 24;   // word within the 23-word (+1 pad) row
        const int d   = w * 32 + lane;   // per-thread bit index (0..767)
        const bool valid = (d < 720);
        int src = 0;
        if (valid) {
            const int i  = d >> 3;              // global pooled position 0..89
            const int cp = 7 - (d & 7);         // c'
            const int c  = 8 * pp + cp;         // reference channel
            int off, lp, ipos;
            if (i < 11)      { off = 0;   lp = 11; ipos = i; }
            else if (i < 22) { off = 176; lp = 11; ipos = i - 11; }
            else if (i < 44) { off = 352; lp = 22; ipos = i - 22; }
            else             { off = 704; lp = 46; ipos = i - 44; }
            src = off + c * lp + ipos;
        }
        const unsigned bal =
            __ballot_sync(0xffffffffu, valid && (p.fc1_w[j * 1440 + src] > 0.0f));
        if (lane == 0) g_wbits[(pp * 64 + j) * 24 + w] = bal;
    }

    // ---- fold BN params (block 0 only) ----
    if (blockIdx.x == 0) {
        const int tid = threadIdx.x;
        if (tid < 64) {
            // FC1 BN with complemented features:
            //   val = inv*(2P - 1440 - m1) + b1 = slope*P + A
            const float inv   = p.g1[tid] * rsqrtf(p.v1[tid] + EPSV);
            const float slope = 2.0f * inv;
            const float A     = p.b1[tid] - inv * (1440.0f + p.m1[tid]);
            float tthr = -A / slope;
            tthr = fmaxf(fminf(tthr, 2.0e9f), -2.0e9f);
            int   T;
            float s;
            if (slope > 0.0f) { T = (int)floorf(tthr);    s =  1.0f; }
            else              { T = (int)ceilf(tthr) - 1; s = -1.0f; }
            const float tb = __int_as_float(T);
            g_fc2t[tid * 8 + 0] = s * p.fc2_w[0 * 64 + tid];
            g_fc2t[tid * 8 + 1] = s * p.fc2_w[1 * 64 + tid];
            g_fc2t[tid * 8 + 2] = s * p.fc2_w[2 * 64 + tid];
            g_fc2t[tid * 8 + 3] = tb;
            g_fc2t[tid * 8 + 4] = s * p.fc2_w[3 * 64 + tid];
            g_fc2t[tid * 8 + 5] = s * p.fc2_w[4 * 64 + tid];
            g_fc2t[tid * 8 + 6] = tb;
            g_fc2t[tid * 8 + 7] = 0.0f;
        }
        if (tid >= 64 && tid < 128) {
            const int id = tid - 64;
            const int br = id >> 4, c = id & 15;
            const float* wc = p.w[br] + c * 3;   // (OUT_CH,1,K) row-major
            const float inv = p.g[br][c] * rsqrtf(p.v[br][c] + EPSV);
            float q[3];
            #pragma unroll
            for (int k = 0; k < 3; k++) {
                const float wk = wc[k];
                const float sg = (wk > 0.0f) ? 1.0f : ((wk < 0.0f) ? -1.0f : 0.0f);
                q[k] = inv * sg;
            }
            const float C = p.b[br][c] - inv * p.m[br][c];
            g_bconsP[id * 4 + 0] = pack2(q[0], q[0]);
            g_bconsP[id * 4 + 1] = pack2(q[1], q[1]);
            g_bconsP[id * 4 + 2] = pack2(q[2], q[2]);
            g_bconsP[id * 4 + 3] = pack2(C,    C);
        }
    }
}

// ---------------------------------------------------------------------------
// Main kernel: 128 threads = 64 samples per CTA (2 threads/sample),
// grid 1024 -> 131072 threads -> ~28 warps/SM resident (single wave).
// __launch_bounds__(128, 7): 73-reg cap. smem ~30.6KB * 7 = 214KB <= 228KB.
// Double-buffered x tile: next phase's global loads issue before current
// phase's compute -> LDG latency hidden; 8 barriers total.
// ---------------------------------------------------------------------------
static constexpr int TPB     = 128;
static constexpr int NSAMP   = 64;   // samples per CTA
static constexpr int XSTRIDE = 28;   // float4-aligned rows (112B)

// Coalesced staging of x[s0+s][XB .. XB+XL), s in [0,64), row stride 28.
template <int L, int XB, int XL>
__device__ __forceinline__ void load_chunk(float* s_x, const float* __restrict__ xg,
                                           int s0, int tid)
{
    constexpr int TOTAL = NSAMP * XL;
    constexpr int ITER  = (TOTAL + TPB - 1) / TPB;
    #pragma unroll
    for (int k = 0; k < ITER; k++) {
        const int idx = tid + k * TPB;
        if ((TOTAL % TPB == 0) || (idx < TOTAL)) {
            const int s    = idx / XL;
            const int pcol = idx - s * XL;
            s_x[s * XSTRIDE + pcol] = __ldg(&xg[(size_t)(s0 + s) * L + XB + pcol]);
        }
    }
}

// Specialized flat float4 staging for L=24 full-row loads: the 64x24 region is
// contiguous in gmem (24%4==0, base s0*24*4B is 16B-aligned for s0 mult of 64),
// and dst layout s*28+col keeps float4 within a row (28%4==0).
// 3 LDG.128 + 3 STS.128 per thread (vs 12+12 scalar).
__device__ __forceinline__ void load24_flat(float* s_x, const float* __restrict__ xg,
                                            int s0, int tid)
{
    const float4* g4 = reinterpret_cast<const float4*>(xg + (size_t)s0 * 24);
    float4*       s4 = reinterpret_cast<float4*>(s_x);
    #pragma unroll
    for (int k = 0; k < 3; k++) {
        const int idx = tid + k * TPB;   // < 384 = 64 rows * 6 float4
        const int s   = idx / 6;
        const int c4  = idx - s * 6;
        s4[s * 7 + c4] = g4[idx];
    }
}

// NP pooled positions (branch-local P0..), 8 channels (this thread's half).
// IBASE = global position base of the branch. Bits: d = 8*(IBASE+P0+ip),
// 8-bit group per position, byte-aligned (shift in {0,8,16,24}).
template <int IBASE, int XB, int P0, int NP>
__device__ __forceinline__ void proc_chunk(uint32_t f[23], const float* xrow,
                                           const unsigned long long* bcp)
{
    constexpr int A0 = 2 * P0 - XB;              // first float needed (>=0)
    constexpr int AL = A0 & ~3;                  // 16B-aligned start
    constexpr int NF = (A0 - AL) + 2 * NP + 2;
    constexpr int NV = (NF + 3) / 4;

    float4 xq[NV];
    const float4* x4 = reinterpret_cast<const float4*>(xrow);
    #pragma unroll
    for (int k = 0; k < NV; k++) xq[k] = x4[AL / 4 + k];
    const float* xvf = reinterpret_cast<const float*>(xq);

    unsigned long long xp[2 * NP + 1];
    #pragma unroll
    for (int i = 0; i < 2 * NP + 1; i++)
        xp[i] = pack2(xvf[A0 - AL + i], xvf[A0 - AL + i + 1]);

    uint32_t mc[NP];
    #pragma unroll
    for (int i = 0; i < NP; i++) mc[i] = 0u;

    #pragma unroll 2
    for (int c = 0; c < 8; c++) {   // this thread's 8 channels
        const ulonglong2 qa = *reinterpret_cast<const ulonglong2*>(bcp + 4 * c);
        const ulonglong2 qb = *reinterpret_cast<const ulonglong2*>(bcp + 4 * c + 2);
        #pragma unroll
        for (int ip = 0; ip < NP; ip++) {
            unsigned long long acc = fma2(qb.x, xp[2 * ip + 2], qb.y);
            acc = fma2(qa.y, xp[2 * ip + 1], acc);
            acc = fma2(qa.x, xp[2 * ip + 0], acc);
            const uint32_t u = (uint32_t)acc & (uint32_t)(acc >> 32);  // LOP3
            mc[ip] = __funnelshift_l(u, mc[ip], 1);                    // SHF
        }
    }
    #pragma unroll
    for (int ip = 0; ip < NP; ip++) {
        const int d = 8 * (IBASE + P0 + ip);     // compile-time
        f[d >> 5] |= mc[ip] << (d & 31);         // shift in {0,8,16,24}
    }
}

__global__ void __launch_bounds__(TPB, 7)
wavebnn_kernel(Ptrs p, float* __restrict__ out)
{
    __shared__ __align__(16) uint32_t s_wbits[2 * 64 * 24];
    __shared__ __align__(16) unsigned long long s_bconsP[64 * 4];
    __shared__ __align__(16) float s_fc2t[64 * 8];
    __shared__ __align__(16) float s_x[2][NSAMP * XSTRIDE];

    const int tid    = threadIdx.x;
    const int parity = tid & 1;
    const int samp   = tid >> 1;               // sample row within CTA
    const int s0     = blockIdx.x * NSAMP;

    // ---- stage constants (fully unrolled, front-batched) ----
    {
        const uint4* gw4 = reinterpret_cast<const uint4*>(g_wbits);
        uint4*       sw4 = reinterpret_cast<uint4*>(s_wbits);
        #pragma unroll
        for (int k = 0; k < 6; k++) sw4[tid + k * TPB] = gw4[tid + k * TPB];
        reinterpret_cast<float4*>(s_fc2t)[tid] =
            reinterpret_cast<const float4*>(g_fc2t)[tid];
        #pragma unroll
        for (int k = 0; k < 2; k++) s_bconsP[tid + k * TPB] = g_bconsP[tid + k * TPB];
    }
    // phase-1 x load overlaps the constant staging
    load24_flat(s_x[0], p.x[0], s0, tid);

    uint32_t f[23];
    #pragma unroll
    for (int i = 0; i < 23; i++) f[i] = 0u;

    const float* xrow0 = &s_x[0][samp * XSTRIDE];
    const float* xrow1 = &s_x[1][samp * XSTRIDE];
    const unsigned long long* bc0 = s_bconsP + parity * 32;  // +8 channels * 4

    // ---- phase 1: cA3 (Lp=11, IBASE=0) [buf0]; prefetch cD3 -> buf1 ----
    __syncthreads();
    load24_flat(s_x[1], p.x[1], s0, tid);
    proc_chunk<0, 0, 0, 6>(f, xrow0, bc0 + 0 * 64);
    proc_chunk<0, 0, 6, 5>(f, xrow0, bc0 + 0 * 64);

    // ---- phase 2: cD3 (IBASE=11) [buf1]; prefetch cD2[0,28) -> buf0 ----
    __syncthreads();
    load_chunk<47, 0, 28>(s_x[0], p.x[2], s0, tid);
    proc_chunk<11, 0, 0, 6>(f, xrow1, bc0 + 1 * 64);
    proc_chunk<11, 0, 6, 5>(f, xrow1, bc0 + 1 * 64);

    // ---- phase 3: cD2 p1 (IBASE=22, p=0..12) [buf0]; prefetch cD2[24,47) ----
    __syncthreads();
    load_chunk<47, 24, 23>(s_x[1], p.x[2], s0, tid);
    proc_chunk<22, 0, 0, 7>(f, xrow0, bc0 + 2 * 64);
    proc_chunk<22, 0, 7, 6>(f, xrow0, bc0 + 2 * 64);

    // ---- phase 4: cD2 p2 (p=13..21) [buf1]; prefetch cD1[0,28) -> buf0 ----
    __syncthreads();
    load_chunk<94, 0, 28>(s_x[0], p.x[3], s0, tid);
    proc_chunk<22, 24, 13, 5>(f, xrow1, bc0 + 2 * 64);
    proc_chunk<22, 24, 18, 4>(f, xrow1, bc0 + 2 * 64);

    // ---- phase 5: cD1 p1 (IBASE=44, p=0..12) [buf0]; prefetch cD1[24,52) ----
    __syncthreads();
    load_chunk<94, 24, 28>(s_x[1], p.x[3], s0, tid);
    proc_chunk<44, 0, 0, 7>(f, xrow0, bc0 + 3 * 64);
    proc_chunk<44, 0, 7, 6>(f, xrow0, bc0 + 3 * 64);

    // ---- phase 6: cD1 p2 (p=13..24) [buf1]; prefetch cD1[48,76) -> buf0 ----
    __syncthreads();
    load_chunk<94, 48, 28>(s_x[0], p.x[3], s0, tid);
    proc_chunk<44, 24, 13, 6>(f, xrow1, bc0 + 3 * 64);
    proc_chunk<44, 24, 19, 6>(f, xrow1, bc0 + 3 * 64);

    // ---- phase 7: cD1 p3 (p=25..36) [buf0]; prefetch cD1[72,94) -> buf1 ----
    __syncthreads();
    load_chunk<94, 72, 22>(s_x[1], p.x[3], s0, tid);
    proc_chunk<44, 48, 25, 6>(f, xrow0, bc0 + 3 * 64);
    proc_chunk<44, 48, 31, 6>(f, xrow0, bc0 + 3 * 64);

    // ---- phase 8: cD1 p4 (p=37..45) [buf1] ----
    __syncthreads();
    proc_chunk<44, 72, 37, 5>(f, xrow1, bc0 + 3 * 64);
    proc_chunk<44, 72, 42, 4>(f, xrow1, bc0 + 3 * 64);

    // ---- FC1: software-pipelined batches of 4 rows.
    // Partial popcounts packed 2x16-bit per word (Ph<=720, pair sum<=1440:
    // no carry across the 16-bit fields) -> 2 SHFLs per 4 rows, and each
    // batch's SHFL results are consumed only after the NEXT batch's popc
    // tree (~130 instrs) -> SHFL latency fully hidden.
    float o0, o1, o2;
    if (parity == 0) { o0 = p.fc2_b[0]; o1 = p.fc2_b[1]; o2 = p.fc2_b[2]; }
    else             { o0 = p.fc2_b[3]; o1 = p.fc2_b[4]; o2 = 0.0f; }

    const uint32_t* wtab = &s_wbits[parity * 64 * 24];

    auto popc4 = [&](int j4, uint32_t pk[2]) {
        #pragma unroll
        for (int q = 0; q < 2; q++) {
            uint32_t pr = 0;
            #pragma unroll
            for (int u = 0; u < 2; u++) {
                const uint32_t* wr = &wtab[(j4 + 2 * q + u) * 24];
                int a0 = 0, a1 = 0;
                #pragma unroll
                for (int w4 = 0; w4 < 5; w4++) {
                    const uint4 ww = *reinterpret_cast<const uint4*>(wr + 4 * w4);
                    a0 += __popc(f[4*w4+0] ^ ww.x) + __popc(f[4*w4+1] ^ ww.y);
                    a1 += __popc(f[4*w4+2] ^ ww.z) + __popc(f[4*w4+3] ^ ww.w);
                }
                a0 += __popc(f[20] ^ wr[20]) + __popc(f[21] ^ wr[21]);
                a1 += __popc(f[22] ^ wr[22]);
                pr |= (uint32_t)(a0 + a1) << (16 * u);
            }
            pk[q] = pr;
        }
    };
    auto epi4 = [&](int j4, const uint32_t s[2]) {
        #pragma unroll
        for (int u = 0; u < 4; u++) {
            const int P = (int)((s[u >> 1] >> (16 * (u & 1))) & 0xffffu);
            const float4 wv =
                *reinterpret_cast<const float4*>(&s_fc2t[(j4 + u) * 8 + parity * 4]);
            const int   T = __float_as_int(parity ? wv.z : wv.w);
            const float h = (P > T) ? 1.0f : -1.0f;        // ISETP+SEL
            o0 = fmaf(h, wv.x, o0);
            o1 = fmaf(h, wv.y, o1);
            if (parity == 0) o2 = fmaf(h, wv.z, o2);       // predicated FFMA
        }
    };

    uint32_t pk[2], sh[2];
    popc4(0, pk);
    sh[0] = pk[0] + __shfl_xor_sync(0xffffffffu, pk[0], 1);
    sh[1] = pk[1] + __shfl_xor_sync(0xffffffffu, pk[1], 1);
    #pragma unroll 1
    for (int j4 = 4; j4 < 64; j4 += 4) {
        uint32_t npk[2];
        popc4(j4, npk);                    // ~130 instrs cover prev SHFL latency
        epi4(j4 - 4, sh);
        sh[0] = npk[0] + __shfl_xor_sync(0xffffffffu, npk[0], 1);
        sh[1] = npk[1] + __shfl_xor_sync(0xffffffffu, npk[1], 1);
    }
    epi4(60, sh);

    const size_t ob = (size_t)(s0 + samp) * 5 + parity * 3;
    out[ob + 0] = o0;
    out[ob + 1] = o1;
    if (parity == 0) out[ob + 2] = o2;
}

// ---------------------------------------------------------------------------
// Launch
// ---------------------------------------------------------------------------
extern "C" void kernel_launch(void* const* d_in, const int* in_sizes, int n_in,
                              void* d_out, int out_size)
{
    (void)n_in; (void)out_size;
    Ptrs p;
    // Disambiguate metadata ordering:
    //  dict order      : per branch [x,w,g,b,m,v]        -> in_sizes[1] == 48
    //  signature order : x*4 then per branch [w,g,b,m,v] -> in_sizes[1] == 65536*24
    const bool dict = (in_sizes[1] == 48);
    for (int br = 0; br < 4; br++) {
        if (dict) {
            p.x[br] = (const float*)d_in[br * 6 + 0];
            p.w[br] = (const float*)d_in[br * 6 + 1];
            p.g[br] = (const float*)d_in[br * 6 + 2];
            p.b[br] = (const float*)d_in[br * 6 + 3];
            p.m[br] = (const float*)d_in[br * 6 + 4];
            p.v[br] = (const float*)d_in[br * 6 + 5];
        } else {
            p.x[br] = (const float*)d_in[br];
            p.w[br] = (const float*)d_in[4 + br * 5 + 0];
            p.g[br] = (const float*)d_in[4 + br * 5 + 1];
            p.b[br] = (const float*)d_in[4 + br * 5 + 2];
            p.m[br] = (const float*)d_in[4 + br * 5 + 3];
            p.v[br] = (const float*)d_in[4 + br * 5 + 4];
        }
    }
    p.fc1_w = (const float*)d_in[24];
    p.g1    = (const float*)d_in[25];
    p.b1    = (const float*)d_in[26];
    p.m1    = (const float*)d_in[27];
    p.v1    = (const float*)d_in[28];
    p.fc2_w = (const float*)d_in[29];
    p.fc2_b = (const float*)d_in[30];

    prep_kernel<<<384, 256>>>(p);
    wavebnn_kernel<<<65536 / NSAMP, TPB>>>(p, (float*)d_out);
}